// round 16
// baseline (speedup 1.0000x reference)
#include <cuda_runtime.h>
#include <stdint.h>
#include <math.h>

#define DD  256
#define TT  128
#define BB  2
#define BT  256
#define LL  8
#define HH  4
#define DHH 64
#define FF  2048
#define NC  2048

typedef unsigned long long ULL;

// ---------------- device scratch ----------------
__device__ float g_vcls[DD];
__device__ float g_scls[HH];
__device__ float g_bias0[DD];      // cls_token + bo
__device__ float g_vf[BT*DD];
__device__ float g_sf[BT*HH];
__device__ float g_x0[NC*DD];
__device__ float g_h2[NC*DD];
__device__ float g_u [NC*FF];
__device__ float g_enc[NC*DD];
__device__ float g_part[8*NC*DD];
__device__ int   g_lstar[BT];

// ---------------- f32x2 / cp.async helpers ----------------
__device__ __forceinline__ ULL dup2(float x){
    ULL r; unsigned u = __float_as_uint(x);
    asm("mov.b64 %0, {%1, %1};" : "=l"(r) : "r"(u));
    return r;
}
__device__ __forceinline__ void fma2(ULL &c, ULL a, ULL b){
    asm("fma.rn.f32x2 %0, %1, %2, %0;" : "+l"(c) : "l"(a), "l"(b));
}
__device__ __forceinline__ float2 unpack2(ULL p){
    unsigned lo, hi;
    asm("mov.b64 {%0, %1}, %2;" : "=r"(lo), "=r"(hi) : "l"(p));
    return make_float2(__uint_as_float(lo), __uint_as_float(hi));
}
__device__ __forceinline__ void cpa16(void* smem, const void* g){
    unsigned s = (unsigned)__cvta_generic_to_shared(smem);
    asm volatile("cp.async.cg.shared.global [%0], [%1], 16;" :: "r"(s), "l"(g));
}
__device__ __forceinline__ void cpa_commit(){
    asm volatile("cp.async.commit_group;" ::: "memory");
}
__device__ __forceinline__ void cpa_wait0(){
    asm volatile("cp.async.wait_group 0;" ::: "memory");
}

__device__ __forceinline__ float blockReduceSum256(float v, float* red){
    int t = threadIdx.x;
    red[t] = v; __syncthreads();
    #pragma unroll
    for (int s = 128; s > 0; s >>= 1){
        if (t < s) red[t] += red[t + s];
        __syncthreads();
    }
    float r = red[0];
    __syncthreads();
    return r;
}

// ---- kP2: CLS precompute (replicated per block, identical bits) + per-frame
//      LN1 + K/V + score, 4 frames/block. (verified R8-R12) -----------------------
__global__ void kP2(const float* __restrict__ frames, const float* __restrict__ cls,
                    const float* __restrict__ Wq, const float* __restrict__ bq,
                    const float* __restrict__ Wk, const float* __restrict__ bk,
                    const float* __restrict__ Wv, const float* __restrict__ bv,
                    const float* __restrict__ bo,
                    const float* __restrict__ g1, const float* __restrict__ b1){
    __shared__ float red[256];
    __shared__ float h[DD];
    __shared__ float hs[4][DD];
    int blk = blockIdx.x;
    int t = threadIdx.x;

    {
        float x = cls[t];
        float mean = blockReduceSum256(x, red) * (1.f/DD);
        float dx = x - mean;
        float var = blockReduceSum256(dx*dx, red) * (1.f/DD);
        float hn = dx * rsqrtf(var + 1e-5f) * g1[t] + b1[t];
        h[t] = hn; __syncthreads();
    }
    float qc, vc;
    {
        float q = bq[t], k = bk[t], v = bv[t];
        #pragma unroll 8
        for (int j = 0; j < DD; j++){
            float hj = h[j];
            q += hj * Wq[j*DD + t];
            k += hj * Wk[j*DD + t];
            v += hj * Wv[j*DD + t];
        }
        qc = q; vc = v;
        red[t] = q * k; __syncthreads();
        if (t < HH){
            float s = 0.f;
            #pragma unroll
            for (int d = 0; d < DHH; d++) s += red[t*DHH + d];
            g_scls[t] = s * 0.125f;
        }
        __syncthreads();
    }
    g_vcls[t] = vc;
    g_bias0[t] = cls[t] + bo[t];

    #pragma unroll
    for (int f = 0; f < 4; f++){
        float x = frames[(blk*4 + f)*DD + t];
        float mean = blockReduceSum256(x, red) * (1.f/DD);
        float dx = x - mean;
        float var = blockReduceSum256(dx*dx, red) * (1.f/DD);
        hs[f][t] = dx * rsqrtf(var + 1e-5f) * g1[t] + b1[t];
    }
    __syncthreads();

    float kk[4], vv[4];
    #pragma unroll
    for (int f = 0; f < 4; f++){ kk[f] = bk[t]; vv[f] = bv[t]; }
    #pragma unroll 4
    for (int j = 0; j < DD; j++){
        float wk = Wk[j*DD + t], wv = Wv[j*DD + t];
        #pragma unroll
        for (int f = 0; f < 4; f++){
            kk[f] += hs[f][j] * wk;
            vv[f] += hs[f][j] * wv;
        }
    }
    #pragma unroll
    for (int f = 0; f < 4; f++)
        g_vf[(blk*4 + f)*DD + t] = vv[f];
    #pragma unroll
    for (int f = 0; f < 4; f++){
        red[t] = qc * kk[f]; __syncthreads();
        if (t < HH){
            float s = 0.f;
            #pragma unroll
            for (int d = 0; d < DHH; d++) s += red[t*DHH + d];
            g_sf[(blk*4 + f)*HH + t] = s * 0.125f;
        }
        __syncthreads();
    }
}

// ---- kAX3: attention + fused o0@Wo (split-4 asc) + bias0 -> x0, + LN2 -> h2
//      (verified R8-R12) -----------------------------------------------------------
__global__ void kAX3(const float* __restrict__ Wo,
                     const float* __restrict__ g2, const float* __restrict__ b2){
    __shared__ float vsh[9][DD];
    __shared__ float sh_s[HH][9];
    __shared__ float wsh[LL][HH][9];
    __shared__ float osh[LL][DD];
    __shared__ float xsh[LL][DD];
    __shared__ float R[LL][DD];
    __shared__ float m8[LL], rs8[LL];
    int blk = blockIdx.x;
    int b = blk >> 7;
    int i = blk & 127;
    int t = threadIdx.x;

    vsh[0][t] = g_vcls[t];
    #pragma unroll
    for (int tt = 0; tt < 8; tt++)
        vsh[tt+1][t] = (i + tt < TT) ? g_vf[(b*TT + i + tt)*DD + t] : 0.f;

    if (t < 36){
        int hh = t / 9, idx = t % 9;
        float s;
        if (idx == 0) s = g_scls[hh];
        else {
            int tt = idx - 1;
            s = (i + tt < TT) ? g_sf[(b*TT + i + tt)*HH + hh] : -1e30f;
        }
        sh_s[hh][idx] = s;
    }
    __syncthreads();

    if (t < 32){
        int l  = (t >> 2) + 1;
        int hh = t & 3;
        float m = sh_s[hh][0];
        for (int tt = 0; tt < l; tt++)
            if (i + tt < TT) m = fmaxf(m, sh_s[hh][tt+1]);
        float e0 = expf(sh_s[hh][0] - m);
        float sum = e0;
        float e[8];
        #pragma unroll
        for (int tt = 0; tt < 8; tt++){
            bool inc = (tt < l) && (i + tt < TT);
            e[tt] = inc ? expf(sh_s[hh][tt+1] - m) : 0.f;
            sum += e[tt];
        }
        float inv = 1.f / sum;
        wsh[l-1][hh][0] = e0 * inv;
        #pragma unroll
        for (int tt = 0; tt < 8; tt++) wsh[l-1][hh][tt+1] = e[tt] * inv;
    }
    __syncthreads();

    int hd = t >> 6;
    #pragma unroll
    for (int l = 0; l < LL; l++){
        float acc = wsh[l][hd][0] * vsh[0][t];
        #pragma unroll
        for (int tt = 0; tt < 8; tt++)
            acc += wsh[l][hd][tt+1] * vsh[tt+1][t];
        osh[l][t] = acc;
    }
    __syncthreads();

    float accA[LL];
    #pragma unroll
    for (int z = 0; z < 4; z++){
        float sz[LL];
        #pragma unroll
        for (int l = 0; l < LL; l++) sz[l] = 0.f;
        #pragma unroll 8
        for (int j = 0; j < 64; j++){
            int kk = z*64 + j;
            float wo = Wo[kk*DD + t];
            #pragma unroll
            for (int l = 0; l < LL; l++)
                sz[l] = fmaf(osh[l][kk], wo, sz[l]);
        }
        if (z == 0){
            #pragma unroll
            for (int l = 0; l < LL; l++) accA[l] = sz[l];
        } else {
            #pragma unroll
            for (int l = 0; l < LL; l++) accA[l] += sz[l];
        }
    }
    float b0 = g_bias0[t];
    #pragma unroll
    for (int l = 0; l < LL; l++){
        float xv = accA[l] + b0;
        xsh[l][t] = xv;
        R[l][t] = xv;
        g_x0[(size_t)(blk*LL + l)*DD + t] = xv;
    }
    __syncthreads();

    #pragma unroll
    for (int s = 128; s > 0; s >>= 1){
        for (int idx = t; idx < LL*s; idx += 256){
            int l = idx / s, tt = idx - l*s;
            R[l][tt] += R[l][tt + s];
        }
        __syncthreads();
    }
    if (t < LL) m8[t] = R[t][0] * (1.f/DD);
    __syncthreads();

    float dxr[LL];
    #pragma unroll
    for (int l = 0; l < LL; l++){
        float dx = xsh[l][t] - m8[l];
        dxr[l] = dx;
        R[l][t] = dx*dx;
    }
    __syncthreads();
    #pragma unroll
    for (int s = 128; s > 0; s >>= 1){
        for (int idx = t; idx < LL*s; idx += 256){
            int l = idx / s, tt = idx - l*s;
            R[l][tt] += R[l][tt + s];
        }
        __syncthreads();
    }
    if (t < LL) rs8[t] = rsqrtf(R[t][0] * (1.f/DD) + 1e-5f);
    __syncthreads();

    float gg = g2[t], bb = b2[t];
    #pragma unroll
    for (int l = 0; l < LL; l++)
        g_h2[(size_t)(blk*LL + l)*DD + t] = dxr[l] * rs8[l] * gg + bb;
}

// ------- wide f32x2 SGEMM (R8/R12-verified for GEMM2): 128x128, LDG staging -------
template<int EPI, bool SPLIT>
__global__ __launch_bounds__(256, 2)
void sgemmW(const float* __restrict__ A, const float* __restrict__ B,
            const float* __restrict__ bias, const float* __restrict__ res,
            float* __restrict__ C, int M, int N, int Kblk, int Ktot){
    __shared__ __align__(16) float As[2][16][132];
    __shared__ __align__(16) float Bs[2][16][128];
    int tid = threadIdx.x;
    int bm = blockIdx.y * 128;
    int bn = blockIdx.x * 128;
    int kOff = SPLIT ? blockIdx.z * Kblk : 0;
    if (SPLIT) C += (size_t)blockIdx.z * M * N;
    int tx = tid & 15, ty = tid >> 4;
    const int KT = Kblk >> 4;

    ULL acc[4][8];
    #pragma unroll
    for (int mp = 0; mp < 4; mp++)
        #pragma unroll
        for (int jj = 0; jj < 8; jj++) acc[mp][jj] = 0ULL;

    float4 pa[2], pb[2];
    auto loadG = [&](int kt){
        #pragma unroll
        for (int i = 0; i < 2; i++){
            int v = tid + i*256;
            int row = v >> 2, kq = (v & 3) * 4;
            pa[i] = *(const float4*)&A[(size_t)(bm + row)*Ktot + kOff + kt*16 + kq];
            int brow = v >> 5, bc = (v & 31) * 4;
            pb[i] = *(const float4*)&B[(size_t)(kOff + kt*16 + brow)*N + bn + bc];
        }
    };
    auto storeS = [&](int buf){
        #pragma unroll
        for (int i = 0; i < 2; i++){
            int v = tid + i*256;
            int row = v >> 2, kq = (v & 3) * 4;
            As[buf][kq+0][row] = pa[i].x;
            As[buf][kq+1][row] = pa[i].y;
            As[buf][kq+2][row] = pa[i].z;
            As[buf][kq+3][row] = pa[i].w;
            int brow = v >> 5, bc = (v & 31) * 4;
            *(float4*)&Bs[buf][brow][bc] = pb[i];
        }
    };

    loadG(0);
    storeS(0);
    __syncthreads();

    for (int kt = 0; kt < KT; kt++){
        int cur = kt & 1;
        if (kt + 1 < KT) loadG(kt + 1);
        #pragma unroll
        for (int k = 0; k < 16; k++){
            ulonglong2 a01 = *(const ulonglong2*)&As[cur][k][ty*8];
            ulonglong2 a23 = *(const ulonglong2*)&As[cur][k][ty*8 + 4];
            ULL am0 = a01.x, am1 = a01.y, am2 = a23.x, am3 = a23.y;
            #pragma unroll
            for (int j = 0; j < 4; j++){
                float2 bf = *(const float2*)&Bs[cur][k][2*(tx + 16*j)];
                ULL b0 = dup2(bf.x), b1 = dup2(bf.y);
                fma2(acc[0][2*j],   am0, b0);
                fma2(acc[1][2*j],   am1, b0);
                fma2(acc[2][2*j],   am2, b0);
                fma2(acc[3][2*j],   am3, b0);
                fma2(acc[0][2*j+1], am0, b1);
                fma2(acc[1][2*j+1], am1, b1);
                fma2(acc[2][2*j+1], am2, b1);
                fma2(acc[3][2*j+1], am3, b1);
            }
        }
        if (kt + 1 < KT) storeS(1 - cur);
        __syncthreads();
    }

    #pragma unroll
    for (int mp = 0; mp < 4; mp++){
        int r0 = bm + ty*8 + 2*mp;
        #pragma unroll
        for (int j = 0; j < 4; j++){
            int col = bn + 2*(tx + 16*j);
            float2 va = unpack2(acc[mp][2*j]);
            float2 vb = unpack2(acc[mp][2*j+1]);
            float2 row0 = make_float2(va.x, vb.x);
            float2 row1 = make_float2(va.y, vb.y);
            if (EPI & 1){
                float2 bx = *(const float2*)&bias[col];
                row0.x += bx.x; row0.y += bx.y;
                row1.x += bx.x; row1.y += bx.y;
            }
            if (EPI & 2){
                float2 ra = *(const float2*)&res[(size_t)r0*N + col];
                float2 rb = *(const float2*)&res[(size_t)(r0+1)*N + col];
                row0.x += ra.x; row0.y += ra.y;
                row1.x += rb.x; row1.y += rb.y;
            }
            if (EPI & 4){
                row0.x = fmaxf(row0.x, 0.f); row0.y = fmaxf(row0.y, 0.f);
                row1.x = fmaxf(row1.x, 0.f); row1.y = fmaxf(row1.y, 0.f);
            }
            *(float2*)&C[(size_t)r0*N + col]     = row0;
            *(float2*)&C[(size_t)(r0+1)*N + col] = row1;
        }
    }
}

// ------- sgemmA64: cp.async f32x2 SGEMM, 128(M)x64(N), BK=32, 3 blocks/SM ---------
// Same per-output k-chain as sgemmA (k strictly ascending, split-K outer) ->
// bitwise identical. acc[8][2] (32 regs) + 4-row A-frag halves (16 regs).
template<int EPI, bool SPLIT>
__global__ __launch_bounds__(256, 3)
void sgemmA64(const float* __restrict__ A, const float* __restrict__ B,
              const float* __restrict__ bias, const float* __restrict__ res,
              float* __restrict__ C, int M, int N, int Kblk, int Ktot){
    __shared__ __align__(16) float As[2][128][36];   // 36.9 KB
    __shared__ __align__(16) float Bs[2][32][64];    // 16 KB
    int tid = threadIdx.x;
    int bm = blockIdx.y * 128;
    int bn = blockIdx.x * 64;
    int kOff = SPLIT ? blockIdx.z * Kblk : 0;
    if (SPLIT) C += (size_t)blockIdx.z * M * N;
    int tx = tid & 15, ty = tid >> 4;
    const int KT = Kblk >> 5;

    ULL acc[8][2];   // [row m][col-pair j]; cols = bn + 2*(tx+16j) .. +1
    #pragma unroll
    for (int m = 0; m < 8; m++){ acc[m][0] = 0ULL; acc[m][1] = 0ULL; }

    auto issue = [&](int kt, int buf){
        #pragma unroll
        for (int i = 0; i < 4; i++){
            int v = tid + i*256;                 // 0..1023 -> A tile 128x32
            int row = v >> 3, kq = (v & 7) * 4;
            cpa16(&As[buf][row][kq],
                  &A[(size_t)(bm + row)*Ktot + kOff + kt*32 + kq]);
        }
        #pragma unroll
        for (int i = 0; i < 2; i++){
            int v = tid + i*256;                 // 0..511 -> B tile 32x64
            int brow = v >> 4, bc = (v & 15) * 4;
            cpa16(&Bs[buf][brow][bc],
                  &B[(size_t)(kOff + kt*32 + brow)*N + bn + bc]);
        }
    };

    issue(0, 0); cpa_commit(); cpa_wait0();
    __syncthreads();

    for (int kt = 0; kt < KT; kt++){
        int cur = kt & 1;
        if (kt + 1 < KT){ issue(kt + 1, 1 - cur); cpa_commit(); }
        #pragma unroll
        for (int k4 = 0; k4 < 8; k4++){
            // process M rows in two halves of 4 to keep reg pressure low
            #pragma unroll
            for (int h = 0; h < 2; h++){
                float4 af[4];
                #pragma unroll
                for (int m = 0; m < 4; m++)
                    af[m] = *(const float4*)&As[cur][ty*8 + h*4 + m][k4*4];
                #pragma unroll
                for (int kk = 0; kk < 4; kk++){
                    int k = k4*4 + kk;
                    ULL bd0 = *(const ULL*)&Bs[cur][k][2*tx];
                    ULL bd1 = *(const ULL*)&Bs[cur][k][2*(tx + 16)];
                    #pragma unroll
                    for (int m = 0; m < 4; m++){
                        float av = (kk == 0) ? af[m].x : (kk == 1) ? af[m].y
                                 : (kk == 2) ? af[m].z : af[m].w;
                        ULL ad = dup2(av);
                        fma2(acc[h*4 + m][0], ad, bd0);
                        fma2(acc[h*4 + m][1], ad, bd1);
                    }
                }
            }
        }
        if (kt + 1 < KT) cpa_wait0();
        __syncthreads();
    }

    #pragma unroll
    for (int m = 0; m < 8; m++){
        int row = bm + ty*8 + m;
        #pragma unroll
        for (int j = 0; j < 2; j++){
            int col = bn + 2*(tx + 16*j);
            float2 v = unpack2(acc[m][j]);
            if (EPI & 1){
                float2 bx = *(const float2*)&bias[col];
                v.x += bx.x; v.y += bx.y;
            }
            if (EPI & 2){
                float2 r = *(const float2*)&res[(size_t)row*N + col];
                v.x += r.x; v.y += r.y;
            }
            if (EPI & 4){ v.x = fmaxf(v.x, 0.f); v.y = fmaxf(v.y, 0.f); }
            *(float2*)&C[(size_t)row*N + col] = v;
        }
    }
}

// --- kRZE (verified R7-R12): reduce(split-8)+b2f+x0 -> enc; fused enc@We1 (split-4);
//     be1+relu; logit dot (kZ order); lstar. One block per (b,i). -----------------
__global__ void kRZE(const float* __restrict__ b2f, const float* __restrict__ We1,
                     const float* __restrict__ be1, const float* __restrict__ We2,
                     const float* __restrict__ be2){
    __shared__ float esh[LL][DD];
    __shared__ float gsh[LL][DD];
    __shared__ float logit[LL];
    int blk = blockIdx.x;
    int t = threadIdx.x;
    const size_t MN = (size_t)NC*DD;

    float bb = b2f[t];
    #pragma unroll
    for (int l = 0; l < LL; l++){
        size_t idx = (size_t)(blk*LL + l)*DD + t;
        float a = g_part[idx];
        #pragma unroll
        for (int z = 1; z < 8; z++) a += g_part[(size_t)z*MN + idx];
        a += bb;
        a += g_x0[idx];
        g_enc[idx] = a;
        esh[l][t] = a;
    }
    __syncthreads();

    float accA[LL];
    #pragma unroll
    for (int z = 0; z < 4; z++){
        float sz[LL];
        #pragma unroll
        for (int l = 0; l < LL; l++) sz[l] = 0.f;
        #pragma unroll 8
        for (int j = 0; j < 64; j++){
            int kk = z*64 + j;
            float w1 = We1[kk*DD + t];
            #pragma unroll
            for (int l = 0; l < LL; l++)
                sz[l] = fmaf(esh[l][kk], w1, sz[l]);
        }
        if (z == 0){
            #pragma unroll
            for (int l = 0; l < LL; l++) accA[l] = sz[l];
        } else {
            #pragma unroll
            for (int l = 0; l < LL; l++) accA[l] += sz[l];
        }
    }
    float be = be1[t];
    #pragma unroll
    for (int l = 0; l < LL; l++){
        float a = accA[l] + be;
        gsh[l][t] = fmaxf(a, 0.f);
    }
    __syncthreads();

    int w = t >> 5, lane = t & 31;
    float s = 0.f;
    #pragma unroll
    for (int j = 0; j < 8; j++){
        int d = lane + 32*j;
        s += gsh[w][d] * We2[d];
    }
    #pragma unroll
    for (int o = 16; o; o >>= 1) s += __shfl_down_sync(0xffffffffu, s, o);
    if (lane == 0) logit[w] = s + be2[0];
    __syncthreads();
    if (t == 0){
        int i = blk & 127;
        int lmax = TT - i; if (lmax > LL) lmax = LL;
        int lstar = lmax;
        for (int l = 1; l <= lmax; l++){
            if (logit[l-1] > 0.f){ lstar = l; break; }
        }
        g_lstar[blk] = lstar;
    }
}

// ---- kS (verified R12): chain with smem-preloaded lstar + output ----
__global__ void kS(float* __restrict__ out, int out_size){
    __shared__ int lsm[TT];
    __shared__ int slot[TT];
    __shared__ int cnts;
    int b = blockIdx.x;
    int t = threadIdx.x;
    if (t < TT) lsm[t] = g_lstar[b*TT + t];
    __syncthreads();
    if (t == 0){
        int i = 0, cnt = 0;
        for (int s = 0; s < TT; s++){
            if (i < TT){
                int ls = lsm[i];
                slot[s] = (b*TT + i)*LL + (ls - 1);
                i += ls;
                cnt++;
            } else {
                slot[s] = -1;
            }
        }
        cnts = cnt;
    }
    __syncthreads();
    for (int s = 0; s < TT; s++){
        int c = slot[s];
        out[(size_t)(b*TT + s)*DD + t] = (c >= 0) ? g_enc[(size_t)c*DD + t] : 0.f;
    }
    if (t == 0 && out_size > BB*TT*DD + b)
        out[BB*TT*DD + b] = (float)cnts;
}

// ---------------- launch ----------------
extern "C" void kernel_launch(void* const* d_in, const int* in_sizes, int n_in,
                              void* d_out, int out_size){
    const float* frames = (const float*)d_in[0];
    const float* cls    = (const float*)d_in[1];
    const float* Wq  = (const float*)d_in[2];  const float* bq  = (const float*)d_in[3];
    const float* Wk  = (const float*)d_in[4];  const float* bk  = (const float*)d_in[5];
    const float* Wv  = (const float*)d_in[6];  const float* bv  = (const float*)d_in[7];
    const float* Wo  = (const float*)d_in[8];  const float* bo  = (const float*)d_in[9];
    const float* ln1g= (const float*)d_in[10]; const float* ln1b= (const float*)d_in[11];
    const float* ln2g= (const float*)d_in[12]; const float* ln2b= (const float*)d_in[13];
    const float* W1  = (const float*)d_in[14]; const float* b1f = (const float*)d_in[15];
    const float* W2  = (const float*)d_in[16]; const float* b2f = (const float*)d_in[17];
    const float* We1 = (const float*)d_in[18]; const float* be1 = (const float*)d_in[19];
    const float* We2 = (const float*)d_in[20]; const float* be2 = (const float*)d_in[21];
    float* out = (float*)d_out;

    float *p_h2, *p_u, *p_part;
    cudaGetSymbolAddress((void**)&p_h2,   g_h2);
    cudaGetSymbolAddress((void**)&p_u,    g_u);
    cudaGetSymbolAddress((void**)&p_part, g_part);

    // 1. CLS (inlined) + per-frame LN1/K/V/scores
    kP2<<<BT/4, 256>>>(frames, cls, Wq, bq, Wk, bk, Wv, bv, bo, ln1g, ln1b);
    // 2. attention + fused o0@Wo + bias0 -> x0, + LN2 -> h2
    kAX3<<<BT, 256>>>(Wo, ln2g, ln2b);
    // 3. u = relu(h2 @ W1 + b1f) — sgemmW (R12 config, best measured)
    sgemmW<5, false><<<dim3(FF/128, NC/128, 1), 256>>>(p_h2, W1, b1f, nullptr, p_u, NC, FF, DD, DD);
    // 4. enc partials: u @ W2 [split-K=8] — sgemmA64 (3 blocks/SM, bitwise = sgemmA)
    sgemmA64<0, true><<<dim3(DD/64, NC/128, 8), 256>>>(p_u, W2, nullptr, nullptr, p_part, NC, DD, 256, FF);
    // 5. fused: reduce+b2f+x0 -> enc; enc@We1; relu; logits; lstar
    kRZE<<<BT, 256>>>(b2f, We1, be1, We2, be2);
    // 6. chain + output
    kS<<<BB, 256>>>(out, out_size);
}

// round 17
// speedup vs baseline: 1.6589x; 1.6589x over previous
#include <cuda_runtime.h>
#include <stdint.h>
#include <math.h>

#define DD  256
#define TT  128
#define BB  2
#define BT  256
#define LL  8
#define HH  4
#define DHH 64
#define FF  2048
#define NC  2048

typedef unsigned long long ULL;

// ---------------- device scratch ----------------
__device__ float g_vcls[DD];
__device__ float g_scls[HH];
__device__ float g_bias0[DD];      // cls_token + bo
__device__ float g_vf[BT*DD];
__device__ float g_sf[BT*HH];
__device__ float g_x0[NC*DD];
__device__ float g_h2[NC*DD];
__device__ float g_u [NC*FF];
__device__ float g_enc[NC*DD];
__device__ float g_part[8*NC*DD];
__device__ int   g_lstar[BT];

// ---------------- f32x2 / cp.async helpers ----------------
__device__ __forceinline__ ULL dup2(float x){
    ULL r; unsigned u = __float_as_uint(x);
    asm("mov.b64 %0, {%1, %1};" : "=l"(r) : "r"(u));
    return r;
}
__device__ __forceinline__ void fma2(ULL &c, ULL a, ULL b){
    asm("fma.rn.f32x2 %0, %1, %2, %0;" : "+l"(c) : "l"(a), "l"(b));
}
__device__ __forceinline__ float2 unpack2(ULL p){
    unsigned lo, hi;
    asm("mov.b64 {%0, %1}, %2;" : "=r"(lo), "=r"(hi) : "l"(p));
    return make_float2(__uint_as_float(lo), __uint_as_float(hi));
}
__device__ __forceinline__ void cpa16(void* smem, const void* g){
    unsigned s = (unsigned)__cvta_generic_to_shared(smem);
    asm volatile("cp.async.cg.shared.global [%0], [%1], 16;" :: "r"(s), "l"(g));
}
__device__ __forceinline__ void cpa_commit(){
    asm volatile("cp.async.commit_group;" ::: "memory");
}
__device__ __forceinline__ void cpa_wait0(){
    asm volatile("cp.async.wait_group 0;" ::: "memory");
}

__device__ __forceinline__ float blockReduceSum256(float v, float* red){
    int t = threadIdx.x;
    red[t] = v; __syncthreads();
    #pragma unroll
    for (int s = 128; s > 0; s >>= 1){
        if (t < s) red[t] += red[t + s];
        __syncthreads();
    }
    float r = red[0];
    __syncthreads();
    return r;
}

// ---- kP2: CLS precompute (replicated per block, identical bits) + per-frame
//      LN1 + K/V + score, 4 frames/block. (verified R8-R12) -----------------------
__global__ void kP2(const float* __restrict__ frames, const float* __restrict__ cls,
                    const float* __restrict__ Wq, const float* __restrict__ bq,
                    const float* __restrict__ Wk, const float* __restrict__ bk,
                    const float* __restrict__ Wv, const float* __restrict__ bv,
                    const float* __restrict__ bo,
                    const float* __restrict__ g1, const float* __restrict__ b1){
    __shared__ float red[256];
    __shared__ float h[DD];
    __shared__ float hs[4][DD];
    int blk = blockIdx.x;
    int t = threadIdx.x;

    {
        float x = cls[t];
        float mean = blockReduceSum256(x, red) * (1.f/DD);
        float dx = x - mean;
        float var = blockReduceSum256(dx*dx, red) * (1.f/DD);
        float hn = dx * rsqrtf(var + 1e-5f) * g1[t] + b1[t];
        h[t] = hn; __syncthreads();
    }
    float qc, vc;
    {
        float q = bq[t], k = bk[t], v = bv[t];
        #pragma unroll 8
        for (int j = 0; j < DD; j++){
            float hj = h[j];
            q += hj * Wq[j*DD + t];
            k += hj * Wk[j*DD + t];
            v += hj * Wv[j*DD + t];
        }
        qc = q; vc = v;
        red[t] = q * k; __syncthreads();
        if (t < HH){
            float s = 0.f;
            #pragma unroll
            for (int d = 0; d < DHH; d++) s += red[t*DHH + d];
            g_scls[t] = s * 0.125f;
        }
        __syncthreads();
    }
    g_vcls[t] = vc;
    g_bias0[t] = cls[t] + bo[t];

    #pragma unroll
    for (int f = 0; f < 4; f++){
        float x = frames[(blk*4 + f)*DD + t];
        float mean = blockReduceSum256(x, red) * (1.f/DD);
        float dx = x - mean;
        float var = blockReduceSum256(dx*dx, red) * (1.f/DD);
        hs[f][t] = dx * rsqrtf(var + 1e-5f) * g1[t] + b1[t];
    }
    __syncthreads();

    float kk[4], vv[4];
    #pragma unroll
    for (int f = 0; f < 4; f++){ kk[f] = bk[t]; vv[f] = bv[t]; }
    #pragma unroll 4
    for (int j = 0; j < DD; j++){
        float wk = Wk[j*DD + t], wv = Wv[j*DD + t];
        #pragma unroll
        for (int f = 0; f < 4; f++){
            kk[f] += hs[f][j] * wk;
            vv[f] += hs[f][j] * wv;
        }
    }
    #pragma unroll
    for (int f = 0; f < 4; f++)
        g_vf[(blk*4 + f)*DD + t] = vv[f];
    #pragma unroll
    for (int f = 0; f < 4; f++){
        red[t] = qc * kk[f]; __syncthreads();
        if (t < HH){
            float s = 0.f;
            #pragma unroll
            for (int d = 0; d < DHH; d++) s += red[t*DHH + d];
            g_sf[(blk*4 + f)*HH + t] = s * 0.125f;
        }
        __syncthreads();
    }
}

// ---- kAX3: attention + fused o0@Wo (split-4 asc) + bias0 -> x0, + LN2 -> h2
//      (verified R8-R12) -----------------------------------------------------------
__global__ void kAX3(const float* __restrict__ Wo,
                     const float* __restrict__ g2, const float* __restrict__ b2){
    __shared__ float vsh[9][DD];
    __shared__ float sh_s[HH][9];
    __shared__ float wsh[LL][HH][9];
    __shared__ float osh[LL][DD];
    __shared__ float xsh[LL][DD];
    __shared__ float R[LL][DD];
    __shared__ float m8[LL], rs8[LL];
    int blk = blockIdx.x;
    int b = blk >> 7;
    int i = blk & 127;
    int t = threadIdx.x;

    vsh[0][t] = g_vcls[t];
    #pragma unroll
    for (int tt = 0; tt < 8; tt++)
        vsh[tt+1][t] = (i + tt < TT) ? g_vf[(b*TT + i + tt)*DD + t] : 0.f;

    if (t < 36){
        int hh = t / 9, idx = t % 9;
        float s;
        if (idx == 0) s = g_scls[hh];
        else {
            int tt = idx - 1;
            s = (i + tt < TT) ? g_sf[(b*TT + i + tt)*HH + hh] : -1e30f;
        }
        sh_s[hh][idx] = s;
    }
    __syncthreads();

    if (t < 32){
        int l  = (t >> 2) + 1;
        int hh = t & 3;
        float m = sh_s[hh][0];
        for (int tt = 0; tt < l; tt++)
            if (i + tt < TT) m = fmaxf(m, sh_s[hh][tt+1]);
        float e0 = expf(sh_s[hh][0] - m);
        float sum = e0;
        float e[8];
        #pragma unroll
        for (int tt = 0; tt < 8; tt++){
            bool inc = (tt < l) && (i + tt < TT);
            e[tt] = inc ? expf(sh_s[hh][tt+1] - m) : 0.f;
            sum += e[tt];
        }
        float inv = 1.f / sum;
        wsh[l-1][hh][0] = e0 * inv;
        #pragma unroll
        for (int tt = 0; tt < 8; tt++) wsh[l-1][hh][tt+1] = e[tt] * inv;
    }
    __syncthreads();

    int hd = t >> 6;
    #pragma unroll
    for (int l = 0; l < LL; l++){
        float acc = wsh[l][hd][0] * vsh[0][t];
        #pragma unroll
        for (int tt = 0; tt < 8; tt++)
            acc += wsh[l][hd][tt+1] * vsh[tt+1][t];
        osh[l][t] = acc;
    }
    __syncthreads();

    float accA[LL];
    #pragma unroll
    for (int z = 0; z < 4; z++){
        float sz[LL];
        #pragma unroll
        for (int l = 0; l < LL; l++) sz[l] = 0.f;
        #pragma unroll 8
        for (int j = 0; j < 64; j++){
            int kk = z*64 + j;
            float wo = Wo[kk*DD + t];
            #pragma unroll
            for (int l = 0; l < LL; l++)
                sz[l] = fmaf(osh[l][kk], wo, sz[l]);
        }
        if (z == 0){
            #pragma unroll
            for (int l = 0; l < LL; l++) accA[l] = sz[l];
        } else {
            #pragma unroll
            for (int l = 0; l < LL; l++) accA[l] += sz[l];
        }
    }
    float b0 = g_bias0[t];
    #pragma unroll
    for (int l = 0; l < LL; l++){
        float xv = accA[l] + b0;
        xsh[l][t] = xv;
        R[l][t] = xv;
        g_x0[(size_t)(blk*LL + l)*DD + t] = xv;
    }
    __syncthreads();

    #pragma unroll
    for (int s = 128; s > 0; s >>= 1){
        for (int idx = t; idx < LL*s; idx += 256){
            int l = idx / s, tt = idx - l*s;
            R[l][tt] += R[l][tt + s];
        }
        __syncthreads();
    }
    if (t < LL) m8[t] = R[t][0] * (1.f/DD);
    __syncthreads();

    float dxr[LL];
    #pragma unroll
    for (int l = 0; l < LL; l++){
        float dx = xsh[l][t] - m8[l];
        dxr[l] = dx;
        R[l][t] = dx*dx;
    }
    __syncthreads();
    #pragma unroll
    for (int s = 128; s > 0; s >>= 1){
        for (int idx = t; idx < LL*s; idx += 256){
            int l = idx / s, tt = idx - l*s;
            R[l][tt] += R[l][tt + s];
        }
        __syncthreads();
    }
    if (t < LL) rs8[t] = rsqrtf(R[t][0] * (1.f/DD) + 1e-5f);
    __syncthreads();

    float gg = g2[t], bb = b2[t];
    #pragma unroll
    for (int l = 0; l < LL; l++)
        g_h2[(size_t)(blk*LL + l)*DD + t] = dxr[l] * rs8[l] * gg + bb;
}

// ------- wide f32x2 SGEMM (R8/R12-verified for GEMM2): 128x128, LDG staging -------
template<int EPI, bool SPLIT>
__global__ __launch_bounds__(256, 2)
void sgemmW(const float* __restrict__ A, const float* __restrict__ B,
            const float* __restrict__ bias, const float* __restrict__ res,
            float* __restrict__ C, int M, int N, int Kblk, int Ktot){
    __shared__ __align__(16) float As[2][16][132];
    __shared__ __align__(16) float Bs[2][16][128];
    int tid = threadIdx.x;
    int bm = blockIdx.y * 128;
    int bn = blockIdx.x * 128;
    int kOff = SPLIT ? blockIdx.z * Kblk : 0;
    if (SPLIT) C += (size_t)blockIdx.z * M * N;
    int tx = tid & 15, ty = tid >> 4;
    const int KT = Kblk >> 4;

    ULL acc[4][8];
    #pragma unroll
    for (int mp = 0; mp < 4; mp++)
        #pragma unroll
        for (int jj = 0; jj < 8; jj++) acc[mp][jj] = 0ULL;

    float4 pa[2], pb[2];
    auto loadG = [&](int kt){
        #pragma unroll
        for (int i = 0; i < 2; i++){
            int v = tid + i*256;
            int row = v >> 2, kq = (v & 3) * 4;
            pa[i] = *(const float4*)&A[(size_t)(bm + row)*Ktot + kOff + kt*16 + kq];
            int brow = v >> 5, bc = (v & 31) * 4;
            pb[i] = *(const float4*)&B[(size_t)(kOff + kt*16 + brow)*N + bn + bc];
        }
    };
    auto storeS = [&](int buf){
        #pragma unroll
        for (int i = 0; i < 2; i++){
            int v = tid + i*256;
            int row = v >> 2, kq = (v & 3) * 4;
            As[buf][kq+0][row] = pa[i].x;
            As[buf][kq+1][row] = pa[i].y;
            As[buf][kq+2][row] = pa[i].z;
            As[buf][kq+3][row] = pa[i].w;
            int brow = v >> 5, bc = (v & 31) * 4;
            *(float4*)&Bs[buf][brow][bc] = pb[i];
        }
    };

    loadG(0);
    storeS(0);
    __syncthreads();

    for (int kt = 0; kt < KT; kt++){
        int cur = kt & 1;
        if (kt + 1 < KT) loadG(kt + 1);
        #pragma unroll
        for (int k = 0; k < 16; k++){
            ulonglong2 a01 = *(const ulonglong2*)&As[cur][k][ty*8];
            ulonglong2 a23 = *(const ulonglong2*)&As[cur][k][ty*8 + 4];
            ULL am0 = a01.x, am1 = a01.y, am2 = a23.x, am3 = a23.y;
            #pragma unroll
            for (int j = 0; j < 4; j++){
                float2 bf = *(const float2*)&Bs[cur][k][2*(tx + 16*j)];
                ULL b0 = dup2(bf.x), b1 = dup2(bf.y);
                fma2(acc[0][2*j],   am0, b0);
                fma2(acc[1][2*j],   am1, b0);
                fma2(acc[2][2*j],   am2, b0);
                fma2(acc[3][2*j],   am3, b0);
                fma2(acc[0][2*j+1], am0, b1);
                fma2(acc[1][2*j+1], am1, b1);
                fma2(acc[2][2*j+1], am2, b1);
                fma2(acc[3][2*j+1], am3, b1);
            }
        }
        if (kt + 1 < KT) storeS(1 - cur);
        __syncthreads();
    }

    #pragma unroll
    for (int mp = 0; mp < 4; mp++){
        int r0 = bm + ty*8 + 2*mp;
        #pragma unroll
        for (int j = 0; j < 4; j++){
            int col = bn + 2*(tx + 16*j);
            float2 va = unpack2(acc[mp][2*j]);
            float2 vb = unpack2(acc[mp][2*j+1]);
            float2 row0 = make_float2(va.x, vb.x);
            float2 row1 = make_float2(va.y, vb.y);
            if (EPI & 1){
                float2 bx = *(const float2*)&bias[col];
                row0.x += bx.x; row0.y += bx.y;
                row1.x += bx.x; row1.y += bx.y;
            }
            if (EPI & 2){
                float2 ra = *(const float2*)&res[(size_t)r0*N + col];
                float2 rb = *(const float2*)&res[(size_t)(r0+1)*N + col];
                row0.x += ra.x; row0.y += ra.y;
                row1.x += rb.x; row1.y += rb.y;
            }
            if (EPI & 4){
                row0.x = fmaxf(row0.x, 0.f); row0.y = fmaxf(row0.y, 0.f);
                row1.x = fmaxf(row1.x, 0.f); row1.y = fmaxf(row1.y, 0.f);
            }
            *(float2*)&C[(size_t)r0*N + col]     = row0;
            *(float2*)&C[(size_t)(r0+1)*N + col] = row1;
        }
    }
}

// ------- cp.async f32x2 SGEMM (R10/R12-verified for GEMM3): 128x128, BK=32 --------
template<int EPI, bool SPLIT>
__global__ __launch_bounds__(256, 2)
void sgemmA(const float* __restrict__ A, const float* __restrict__ B,
            const float* __restrict__ bias, const float* __restrict__ res,
            float* __restrict__ C, int M, int N, int Kblk, int Ktot){
    __shared__ __align__(16) float As[2][128][36];
    __shared__ __align__(16) float Bs[2][32][128];
    int tid = threadIdx.x;
    int bm = blockIdx.y * 128;
    int bn = blockIdx.x * 128;
    int kOff = SPLIT ? blockIdx.z * Kblk : 0;
    if (SPLIT) C += (size_t)blockIdx.z * M * N;
    int tx = tid & 15, ty = tid >> 4;
    const int KT = Kblk >> 5;

    ULL acc[8][4];
    #pragma unroll
    for (int m = 0; m < 8; m++)
        #pragma unroll
        for (int j = 0; j < 4; j++) acc[m][j] = 0ULL;

    auto issue = [&](int kt, int buf){
        #pragma unroll
        for (int i = 0; i < 4; i++){
            int v = tid + i*256;
            int row = v >> 3, kq = (v & 7) * 4;
            cpa16(&As[buf][row][kq],
                  &A[(size_t)(bm + row)*Ktot + kOff + kt*32 + kq]);
        }
        #pragma unroll
        for (int i = 0; i < 4; i++){
            int v = tid + i*256;
            int brow = v >> 5, bc = (v & 31) * 4;
            cpa16(&Bs[buf][brow][bc],
                  &B[(size_t)(kOff + kt*32 + brow)*N + bn + bc]);
        }
    };

    issue(0, 0); cpa_commit(); cpa_wait0();
    __syncthreads();

    for (int kt = 0; kt < KT; kt++){
        int cur = kt & 1;
        if (kt + 1 < KT){ issue(kt + 1, 1 - cur); cpa_commit(); }
        #pragma unroll
        for (int k4 = 0; k4 < 8; k4++){
            float4 af[8];
            #pragma unroll
            for (int m = 0; m < 8; m++)
                af[m] = *(const float4*)&As[cur][ty*8 + m][k4*4];
            #pragma unroll
            for (int kk = 0; kk < 4; kk++){
                int k = k4*4 + kk;
                ULL bd[4];
                #pragma unroll
                for (int j = 0; j < 4; j++)
                    bd[j] = *(const ULL*)&Bs[cur][k][2*(tx + 16*j)];
                #pragma unroll
                for (int m = 0; m < 8; m++){
                    float av = (kk == 0) ? af[m].x : (kk == 1) ? af[m].y
                             : (kk == 2) ? af[m].z : af[m].w;
                    ULL ad = dup2(av);
                    #pragma unroll
                    for (int j = 0; j < 4; j++) fma2(acc[m][j], ad, bd[j]);
                }
            }
        }
        if (kt + 1 < KT) cpa_wait0();
        __syncthreads();
    }

    #pragma unroll
    for (int m = 0; m < 8; m++){
        int row = bm + ty*8 + m;
        #pragma unroll
        for (int j = 0; j < 4; j++){
            int col = bn + 2*(tx + 16*j);
            float2 v = unpack2(acc[m][j]);
            if (EPI & 1){
                float2 bx = *(const float2*)&bias[col];
                v.x += bx.x; v.y += bx.y;
            }
            if (EPI & 2){
                float2 r = *(const float2*)&res[(size_t)row*N + col];
                v.x += r.x; v.y += r.y;
            }
            if (EPI & 4){ v.x = fmaxf(v.x, 0.f); v.y = fmaxf(v.y, 0.f); }
            *(float2*)&C[(size_t)row*N + col] = v;
        }
    }
}

// --- kRZE (verified R7-R12): reduce(split-8)+b2f+x0 -> enc; fused enc@We1 (split-4);
//     be1+relu; logit dot (kZ order); lstar. One block per (b,i). -----------------
__global__ void kRZE(const float* __restrict__ b2f, const float* __restrict__ We1,
                     const float* __restrict__ be1, const float* __restrict__ We2,
                     const float* __restrict__ be2){
    __shared__ float esh[LL][DD];
    __shared__ float gsh[LL][DD];
    __shared__ float logit[LL];
    int blk = blockIdx.x;
    int t = threadIdx.x;
    const size_t MN = (size_t)NC*DD;

    float bb = b2f[t];
    #pragma unroll
    for (int l = 0; l < LL; l++){
        size_t idx = (size_t)(blk*LL + l)*DD + t;
        float a = g_part[idx];
        #pragma unroll
        for (int z = 1; z < 8; z++) a += g_part[(size_t)z*MN + idx];
        a += bb;
        a += g_x0[idx];
        g_enc[idx] = a;
        esh[l][t] = a;
    }
    __syncthreads();

    float accA[LL];
    #pragma unroll
    for (int z = 0; z < 4; z++){
        float sz[LL];
        #pragma unroll
        for (int l = 0; l < LL; l++) sz[l] = 0.f;
        #pragma unroll 8
        for (int j = 0; j < 64; j++){
            int kk = z*64 + j;
            float w1 = We1[kk*DD + t];
            #pragma unroll
            for (int l = 0; l < LL; l++)
                sz[l] = fmaf(esh[l][kk], w1, sz[l]);
        }
        if (z == 0){
            #pragma unroll
            for (int l = 0; l < LL; l++) accA[l] = sz[l];
        } else {
            #pragma unroll
            for (int l = 0; l < LL; l++) accA[l] += sz[l];
        }
    }
    float be = be1[t];
    #pragma unroll
    for (int l = 0; l < LL; l++){
        float a = accA[l] + be;
        gsh[l][t] = fmaxf(a, 0.f);
    }
    __syncthreads();

    int w = t >> 5, lane = t & 31;
    float s = 0.f;
    #pragma unroll
    for (int j = 0; j < 8; j++){
        int d = lane + 32*j;
        s += gsh[w][d] * We2[d];
    }
    #pragma unroll
    for (int o = 16; o; o >>= 1) s += __shfl_down_sync(0xffffffffu, s, o);
    if (lane == 0) logit[w] = s + be2[0];
    __syncthreads();
    if (t == 0){
        int i = blk & 127;
        int lmax = TT - i; if (lmax > LL) lmax = LL;
        int lstar = lmax;
        for (int l = 1; l <= lmax; l++){
            if (logit[l-1] > 0.f){ lstar = l; break; }
        }
        g_lstar[blk] = lstar;
    }
}

// ---- kS2: chain (replicated per block, identical ints) + parallel output ----
// 32 blocks per batch; each recomputes the chain from smem-preloaded lstar and
// writes 4 slots. Float bits copied are identical to R12's kS.
#define SUBB 32
__global__ void kS2(float* __restrict__ out, int out_size){
    __shared__ int lsm[TT];
    __shared__ int slot[TT];
    __shared__ int cnts;
    int b   = blockIdx.x / SUBB;
    int sub = blockIdx.x % SUBB;
    int t = threadIdx.x;
    if (t < TT) lsm[t] = g_lstar[b*TT + t];
    __syncthreads();
    if (t == 0){
        int i = 0, cnt = 0;
        for (int s = 0; s < TT; s++){
            if (i < TT){
                int ls = lsm[i];
                slot[s] = (b*TT + i)*LL + (ls - 1);
                i += ls;
                cnt++;
            } else {
                slot[s] = -1;
            }
        }
        cnts = cnt;
    }
    __syncthreads();
    #pragma unroll
    for (int q = 0; q < TT/SUBB; q++){
        int s = sub*(TT/SUBB) + q;
        int c = slot[s];
        out[(size_t)(b*TT + s)*DD + t] = (c >= 0) ? g_enc[(size_t)c*DD + t] : 0.f;
    }
    if (sub == 0 && t == 0 && out_size > BB*TT*DD + b)
        out[BB*TT*DD + b] = (float)cnts;
}

// ---------------- launch ----------------
extern "C" void kernel_launch(void* const* d_in, const int* in_sizes, int n_in,
                              void* d_out, int out_size){
    const float* frames = (const float*)d_in[0];
    const float* cls    = (const float*)d_in[1];
    const float* Wq  = (const float*)d_in[2];  const float* bq  = (const float*)d_in[3];
    const float* Wk  = (const float*)d_in[4];  const float* bk  = (const float*)d_in[5];
    const float* Wv  = (const float*)d_in[6];  const float* bv  = (const float*)d_in[7];
    const float* Wo  = (const float*)d_in[8];  const float* bo  = (const float*)d_in[9];
    const float* ln1g= (const float*)d_in[10]; const float* ln1b= (const float*)d_in[11];
    const float* ln2g= (const float*)d_in[12]; const float* ln2b= (const float*)d_in[13];
    const float* W1  = (const float*)d_in[14]; const float* b1f = (const float*)d_in[15];
    const float* W2  = (const float*)d_in[16]; const float* b2f = (const float*)d_in[17];
    const float* We1 = (const float*)d_in[18]; const float* be1 = (const float*)d_in[19];
    const float* We2 = (const float*)d_in[20]; const float* be2 = (const float*)d_in[21];
    float* out = (float*)d_out;

    float *p_h2, *p_u, *p_part;
    cudaGetSymbolAddress((void**)&p_h2,   g_h2);
    cudaGetSymbolAddress((void**)&p_u,    g_u);
    cudaGetSymbolAddress((void**)&p_part, g_part);

    // 1. CLS (inlined) + per-frame LN1/K/V/scores
    kP2<<<BT/4, 256>>>(frames, cls, Wq, bq, Wk, bk, Wv, bv, bo, ln1g, ln1b);
    // 2. attention + fused o0@Wo + bias0 -> x0, + LN2 -> h2
    kAX3<<<BT, 256>>>(Wo, ln2g, ln2b);
    // 3. u = relu(h2 @ W1 + b1f) — sgemmW (best measured for GEMM2)
    sgemmW<5, false><<<dim3(FF/128, NC/128, 1), 256>>>(p_h2, W1, b1f, nullptr, p_u, NC, FF, DD, DD);
    // 4. enc partials: u @ W2 [split-K=8] — sgemmA (best measured for GEMM3)
    sgemmA<0, true><<<dim3(DD/128, NC/128, 8), 256>>>(p_u, W2, nullptr, nullptr, p_part, NC, DD, 256, FF);
    // 5. fused: reduce+b2f+x0 -> enc; enc@We1; relu; logits; lstar
    kRZE<<<BT, 256>>>(b2f, We1, be1, We2, be2);
    // 6. chain (replicated) + parallel output gather
    kS2<<<BB*SUBB, 256>>>(out, out_size);
}